// round 2
// baseline (speedup 1.0000x reference)
#include <cuda_runtime.h>
#include <math.h>

// ---------------- problem constants ----------------
#define Bc    32
#define Lc    64
#define Sc    64          // number of steps
#define SBc   2048        // Sc*Bc
#define ROWSc 131072      // Sc*Bc*Lc
#define Dc    512
#define Hc    8
#define HDc   64
#define NLc   8
#define KCB   8192
#define Zc    32
#define DFFc  2048
#define D3c   1536

// ---------------- scratch (device globals, no allocs) ----------------
__device__ float g_h  [(size_t)ROWSc * Dc];    // hidden state  [s][b][l][d]
__device__ float g_big[(size_t)ROWSc * DFFc];  // qkv (x1536) / ffn hidden (x2048)
__device__ float g_a  [(size_t)ROWSc * Dc];    // attention output
__device__ float g_bf [(size_t)ROWSc * Dc];    // proj outputs
__device__ float g_ctx [(size_t)SBc * Dc];     // ctx_h0 (B*L x D)
__device__ float g_memh[(size_t)SBc * Dc];     // mem_h per (s,b)
__device__ float g_vmem[(size_t)SBc * Dc];     // CA value vector
__device__ float g_cav [(size_t)SBc * Dc];     // CA output vector (broadcast)
__device__ int   g_idx [SBc];

// ---------------- SGEMM: C[M,N] = A[M,K] @ W[K,N](col slice) + bias ----------------
// 128x128 tile, BK=8, 256 threads, 8x8 per thread. M%128==0, N%128==0, K%8==0.
__global__ __launch_bounds__(256) void sgemm_kernel(
    const float* __restrict__ A, int lda,
    const float* __restrict__ W, int ldw, int wcol0,
    const float* __restrict__ bias,
    float* __restrict__ C, int ldc,
    int K, int relu)
{
    __shared__ float As[8][128];
    __shared__ float Bs[8][128];
    const int tid = threadIdx.x;
    const int tx = tid & 15;
    const int ty = tid >> 4;
    const size_t rowBase = (size_t)blockIdx.y * 128;
    const int    colBase = blockIdx.x * 128;

    const int arow = tid >> 1;
    const int acol = (tid & 1) << 2;
    const int brow = tid >> 5;
    const int bcol = (tid & 31) << 2;

    const float* Ap = A + (rowBase + arow) * (size_t)lda + acol;
    const float* Wp = W + (size_t)brow * ldw + wcol0 + colBase + bcol;

    float acc[8][8];
#pragma unroll
    for (int i = 0; i < 8; i++)
#pragma unroll
        for (int j = 0; j < 8; j++) acc[i][j] = 0.f;

    for (int k0 = 0; k0 < K; k0 += 8) {
        float4 av = *reinterpret_cast<const float4*>(Ap + k0);
        As[acol + 0][arow] = av.x;
        As[acol + 1][arow] = av.y;
        As[acol + 2][arow] = av.z;
        As[acol + 3][arow] = av.w;
        float4 wv = *reinterpret_cast<const float4*>(Wp + (size_t)k0 * ldw);
        *reinterpret_cast<float4*>(&Bs[brow][bcol]) = wv;
        __syncthreads();
#pragma unroll
        for (int k = 0; k < 8; k++) {
            float ra[8], rb[8];
            float4 a0 = *reinterpret_cast<const float4*>(&As[k][ty * 8]);
            float4 a1 = *reinterpret_cast<const float4*>(&As[k][ty * 8 + 4]);
            float4 b0 = *reinterpret_cast<const float4*>(&Bs[k][tx * 8]);
            float4 b1 = *reinterpret_cast<const float4*>(&Bs[k][tx * 8 + 4]);
            ra[0]=a0.x; ra[1]=a0.y; ra[2]=a0.z; ra[3]=a0.w;
            ra[4]=a1.x; ra[5]=a1.y; ra[6]=a1.z; ra[7]=a1.w;
            rb[0]=b0.x; rb[1]=b0.y; rb[2]=b0.z; rb[3]=b0.w;
            rb[4]=b1.x; rb[5]=b1.y; rb[6]=b1.z; rb[7]=b1.w;
#pragma unroll
            for (int i = 0; i < 8; i++)
#pragma unroll
                for (int j = 0; j < 8; j++)
                    acc[i][j] = fmaf(ra[i], rb[j], acc[i][j]);
        }
        __syncthreads();
    }

#pragma unroll
    for (int i = 0; i < 8; i++) {
        size_t row = rowBase + ty * 8 + i;
#pragma unroll
        for (int j = 0; j < 8; j++) {
            int col = colBase + tx * 8 + j;
            float v = acc[i][j] + bias[col];
            if (relu) v = fmaxf(v, 0.f);
            C[row * (size_t)ldc + col] = v;
        }
    }
}

// ---------------- masked self-attention, one block per (s*B+b, head) ----------------
// smem: Qs(64x65) Ks(64x65) Vs(64x64) Ss(64x64) = 66048 bytes (dynamic)
#define ATTN_SMEM 66048
__global__ void attn_kernel(const float* __restrict__ qkv, float* __restrict__ out)
{
    extern __shared__ float sm[];
    float* Qs = sm;
    float* Ks = sm + 4160;
    float* Vs = sm + 8320;
    float* Ss = sm + 12416;
    const int sb = blockIdx.x;
    const int s  = sb >> 5;            // step = sb / B
    const int head = blockIdx.y;
    const int tid = threadIdx.x;
    const size_t rowbase = (size_t)sb * Lc;
    const float* base = qkv + rowbase * D3c + head * HDc;

    for (int idx = tid; idx < Lc * HDc; idx += 256) {
        int l = idx >> 6, d = idx & 63;
        const float* p = base + (size_t)l * D3c;
        Qs[l * 65 + d] = p[d];
        Ks[l * 65 + d] = p[Dc + d];
        Vs[l * 64 + d] = p[2 * Dc + d];
    }
    __syncthreads();

    for (int e = tid; e < Lc * Lc; e += 256) {
        int q = e >> 6, k = e & 63;
        float acc = 0.f;
#pragma unroll
        for (int d = 0; d < HDc; d++)
            acc = fmaf(Qs[q * 65 + d], Ks[k * 65 + d], acc);
        Ss[e] = (k <= s) ? acc * 0.125f : -1e9f;
    }
    __syncthreads();

    const int warp = tid >> 5, lane = tid & 31;
    for (int q = warp * 8; q < warp * 8 + 8; q++) {
        float v0 = Ss[q * 64 + lane];
        float v1 = Ss[q * 64 + 32 + lane];
        float m = fmaxf(v0, v1);
#pragma unroll
        for (int o = 16; o; o >>= 1) m = fmaxf(m, __shfl_xor_sync(0xffffffffu, m, o));
        float e0 = expf(v0 - m);
        float e1 = expf(v1 - m);
        float sum = e0 + e1;
#pragma unroll
        for (int o = 16; o; o >>= 1) sum += __shfl_xor_sync(0xffffffffu, sum, o);
        float inv = 1.f / sum;
        Ss[q * 64 + lane]      = e0 * inv;
        Ss[q * 64 + 32 + lane] = e1 * inv;
    }
    __syncthreads();

    for (int e = tid; e < Lc * HDc; e += 256) {
        int q = e >> 6, d = e & 63;
        float acc = 0.f;
#pragma unroll
        for (int k = 0; k < Lc; k++)
            acc = fmaf(Ss[q * 64 + k], Vs[k * 64 + d], acc);
        out[(rowbase + q) * Dc + head * HDc + d] = acc;
    }
}

// ---------------- residual + LayerNorm (in place on h) ----------------
// bcast=1: t row index = r / L (CA broadcast)
__global__ void ln_kernel(float* __restrict__ h, const float* __restrict__ t,
                          const float* __restrict__ g, const float* __restrict__ bb,
                          int bcast)
{
    __shared__ float red[8];
    const int r = blockIdx.x;
    const int tid = threadIdx.x;
    float* hr = h + (size_t)r * Dc;
    const float* tr = t + (size_t)(bcast ? (r >> 6) : r) * Dc;
    float x[4];
    float sum = 0.f;
#pragma unroll
    for (int i = 0; i < 4; i++) { x[i] = hr[tid + i * 128] + tr[tid + i * 128]; sum += x[i]; }
#pragma unroll
    for (int o = 16; o; o >>= 1) sum += __shfl_xor_sync(0xffffffffu, sum, o);
    if ((tid & 31) == 0) red[tid >> 5] = sum;
    __syncthreads();
    float mean = (red[0] + red[1] + red[2] + red[3]) * (1.f / 512.f);
    float vs = 0.f;
#pragma unroll
    for (int i = 0; i < 4; i++) { float d = x[i] - mean; vs = fmaf(d, d, vs); }
#pragma unroll
    for (int o = 16; o; o >>= 1) vs += __shfl_xor_sync(0xffffffffu, vs, o);
    if ((tid & 31) == 0) red[4 + (tid >> 5)] = vs;
    __syncthreads();
    float var = (red[4] + red[5] + red[6] + red[7]) * (1.f / 512.f);
    float inv = rsqrtf(var + 1e-5f);
#pragma unroll
    for (int i = 0; i < 4; i++)
        hr[tid + i * 128] = (x[i] - mean) * inv * g[tid + i * 128] + bb[tid + i * 128];
}

// ---------------- ctx_h0 = x_full[:, :L] @ W_in + b_in + PE ----------------
__global__ void build_ctx_kernel(const float* __restrict__ x,
                                 const float* __restrict__ Win, const float* __restrict__ bin,
                                 float* __restrict__ ctx)
{
    __shared__ float xv[32];
    const int r = blockIdx.x;           // b*L + l
    const int b = r >> 6, l = r & 63;
    if (threadIdx.x < 32)
        xv[threadIdx.x] = (l == 0) ? 0.f : x[((size_t)b * Lc + (l - 1)) * Zc + threadIdx.x];
    __syncthreads();
    const float LOG1E4 = 9.210340371976184f;
    for (int d = threadIdx.x; d < Dc; d += 128) {
        float acc = bin[d];
#pragma unroll
        for (int z = 0; z < Zc; z++)
            acc = fmaf(xv[z], Win[z * Dc + d], acc);
        int d2 = d & ~1;
        float freq = expf(-LOG1E4 * (float)d2 * (1.f / 512.f));
        float ang = (float)l * freq;
        acc += (d & 1) ? cosf(ang) : sinf(ang);
        ctx[(size_t)r * Dc + d] = acc;
    }
}

// ---------------- VQ argmin over codebook ----------------
__global__ void vq_kernel(const float* __restrict__ x, const float* __restrict__ cb,
                          int* __restrict__ idx)
{
    __shared__ float mv[32];
    __shared__ float sd[256];
    __shared__ int   si[256];
    const int sb = blockIdx.x;          // s*B + b
    const int s = sb >> 5, b = sb & 31;
    const int tid = threadIdx.x;
    if (tid < 32) mv[tid] = x[((size_t)b * Lc + s) * Zc + tid];  // mem = x[b, s]
    __syncthreads();
    float bd = 3.4e38f; int bi = 0x7fffffff;
    for (int k = tid; k < KCB; k += 256) {
        const float* c = cb + (size_t)k * Zc;
        float d2 = 0.f;
#pragma unroll
        for (int z = 0; z < Zc; z++) { float df = mv[z] - c[z]; d2 = fmaf(df, df, d2); }
        if (d2 < bd || (d2 == bd && k < bi)) { bd = d2; bi = k; }
    }
    sd[tid] = bd; si[tid] = bi;
    __syncthreads();
    for (int off = 128; off; off >>= 1) {
        if (tid < off) {
            if (sd[tid + off] < sd[tid] ||
                (sd[tid + off] == sd[tid] && si[tid + off] < si[tid])) {
                sd[tid] = sd[tid + off]; si[tid] = si[tid + off];
            }
        }
        __syncthreads();
    }
    if (tid == 0) idx[sb] = si[0];
}

// ---------------- mem_h = codebook[idx] @ W_in + b_in ----------------
__global__ void build_memh_kernel(const float* __restrict__ cb, const int* __restrict__ idx,
                                  const float* __restrict__ Win, const float* __restrict__ bin,
                                  float* __restrict__ memh)
{
    __shared__ float qv[32];
    const int sb = blockIdx.x;
    if (threadIdx.x < 32)
        qv[threadIdx.x] = cb[(size_t)idx[sb] * Zc + threadIdx.x];
    __syncthreads();
    for (int d = threadIdx.x; d < Dc; d += 128) {
        float acc = bin[d];
#pragma unroll
        for (int z = 0; z < Zc; z++)
            acc = fmaf(qv[z], Win[z * Dc + d], acc);
        memh[(size_t)sb * Dc + d] = acc;
    }
}

// ---------------- broadcast ctx_h0 to all steps ----------------
__global__ void bcast_kernel(const float* __restrict__ ctx, float* __restrict__ h)
{
    size_t i = (size_t)blockIdx.x * 256 + threadIdx.x;
    h[i] = ctx[i & (size_t)(SBc * Dc - 1)];   // SBc*Dc = 2^20
}

// ---------------- final: LN(h[s,b,l=s]) @ W_out + b_out -> out[b,s,:] ----------------
__global__ void final_kernel(const float* __restrict__ h,
                             const float* __restrict__ g, const float* __restrict__ bb,
                             const float* __restrict__ Wout, const float* __restrict__ bout,
                             float* __restrict__ out)
{
    __shared__ float red[8];
    __shared__ float tv[512];
    __shared__ float part[128];
    const int sb = blockIdx.x;
    const int s = sb >> 5, b = sb & 31;
    const int tid = threadIdx.x;
    const float* hr = h + ((size_t)sb * Lc + s) * Dc;
    float x[4]; float sum = 0.f;
#pragma unroll
    for (int i = 0; i < 4; i++) { x[i] = hr[tid + i * 128]; sum += x[i]; }
#pragma unroll
    for (int o = 16; o; o >>= 1) sum += __shfl_xor_sync(0xffffffffu, sum, o);
    if ((tid & 31) == 0) red[tid >> 5] = sum;
    __syncthreads();
    float mean = (red[0] + red[1] + red[2] + red[3]) * (1.f / 512.f);
    float vs = 0.f;
#pragma unroll
    for (int i = 0; i < 4; i++) { float d = x[i] - mean; vs = fmaf(d, d, vs); }
#pragma unroll
    for (int o = 16; o; o >>= 1) vs += __shfl_xor_sync(0xffffffffu, vs, o);
    if ((tid & 31) == 0) red[4 + (tid >> 5)] = vs;
    __syncthreads();
    float var = (red[4] + red[5] + red[6] + red[7]) * (1.f / 512.f);
    float inv = rsqrtf(var + 1e-5f);
#pragma unroll
    for (int i = 0; i < 4; i++)
        tv[tid + i * 128] = (x[i] - mean) * inv * g[tid + i * 128] + bb[tid + i * 128];
    __syncthreads();
    const int z = tid & 31, c = tid >> 5;
    float acc = 0.f;
    for (int k = c * 128; k < c * 128 + 128; k++)
        acc = fmaf(tv[k], Wout[(size_t)k * Zc + z], acc);
    part[tid] = acc;
    __syncthreads();
    if (tid < 32)
        out[((size_t)b * Lc + s) * Zc + z] =
            part[z] + part[32 + z] + part[64 + z] + part[96 + z] + bout[z];
}

// ---------------- host ----------------
static inline void gemm(const float* A, int lda, const float* W, int ldw, int wcol0,
                        const float* bias, float* C, int ldc, int M, int N, int K, int relu)
{
    dim3 grid(N / 128, M / 128);
    sgemm_kernel<<<grid, 256>>>(A, lda, W, ldw, wcol0, bias, C, ldc, K, relu);
}

extern "C" void kernel_launch(void* const* d_in, const int* in_sizes, int n_in,
                              void* d_out, int out_size)
{
    const float* x        = (const float*)d_in[0];
    const float* codebook = (const float*)d_in[1];
    const float* W_in     = (const float*)d_in[2];
    const float* b_in     = (const float*)d_in[3];
    const float* sa_qkv_w = (const float*)d_in[4];
    const float* sa_qkv_b = (const float*)d_in[5];
    const float* sa_out_w = (const float*)d_in[6];
    const float* sa_out_b = (const float*)d_in[7];
    const float* ca_qkv_w = (const float*)d_in[8];
    const float* ca_qkv_b = (const float*)d_in[9];
    const float* ca_out_w = (const float*)d_in[10];
    const float* ca_out_b = (const float*)d_in[11];
    const float* ff1_w    = (const float*)d_in[12];
    const float* ff1_b    = (const float*)d_in[13];
    const float* ff2_w    = (const float*)d_in[14];
    const float* ff2_b    = (const float*)d_in[15];
    const float* ln1_g    = (const float*)d_in[16];
    const float* ln1_b    = (const float*)d_in[17];
    const float* ln2_g    = (const float*)d_in[18];
    const float* ln2_b    = (const float*)d_in[19];
    const float* ln3_g    = (const float*)d_in[20];
    const float* ln3_b    = (const float*)d_in[21];
    const float* ln_g     = (const float*)d_in[22];
    const float* ln_b     = (const float*)d_in[23];
    const float* W_out    = (const float*)d_in[24];
    const float* b_out    = (const float*)d_in[25];
    float* out = (float*)d_out;

    float *h, *big, *a, *bf, *ctx, *memh, *vmem, *cav; int* idx;
    cudaGetSymbolAddress((void**)&h,    g_h);
    cudaGetSymbolAddress((void**)&big,  g_big);
    cudaGetSymbolAddress((void**)&a,    g_a);
    cudaGetSymbolAddress((void**)&bf,   g_bf);
    cudaGetSymbolAddress((void**)&ctx,  g_ctx);
    cudaGetSymbolAddress((void**)&memh, g_memh);
    cudaGetSymbolAddress((void**)&vmem, g_vmem);
    cudaGetSymbolAddress((void**)&cav,  g_cav);
    cudaGetSymbolAddress((void**)&idx,  g_idx);

    cudaFuncSetAttribute(attn_kernel, cudaFuncAttributeMaxDynamicSharedMemorySize, ATTN_SMEM);

    build_ctx_kernel<<<SBc, 128>>>(x, W_in, b_in, ctx);
    vq_kernel<<<SBc, 256>>>(x, codebook, idx);
    build_memh_kernel<<<SBc, 128>>>(codebook, idx, W_in, b_in, memh);
    bcast_kernel<<<(ROWSc * (size_t)Dc) / 256, 256>>>(ctx, h);

    for (int l = 0; l < NLc; l++) {
        // --- self-attention ---
        gemm(h, Dc, sa_qkv_w + (size_t)l * Dc * D3c, D3c, 0,
             sa_qkv_b + (size_t)l * D3c, big, D3c, ROWSc, D3c, Dc, 0);
        attn_kernel<<<dim3(SBc, Hc), 256, ATTN_SMEM>>>(big, a);
        gemm(a, Dc, sa_out_w + (size_t)l * Dc * Dc, Dc, 0,
             sa_out_b + (size_t)l * Dc, bf, Dc, ROWSc, Dc, Dc, 0);
        ln_kernel<<<ROWSc, 128>>>(h, bf, ln1_g + (size_t)l * Dc, ln1_b + (size_t)l * Dc, 0);

        // --- cross-attention (softmax over 1 key == identity -> pure value path) ---
        gemm(memh, Dc, ca_qkv_w + (size_t)l * Dc * D3c, D3c, 2 * Dc,
             ca_qkv_b + (size_t)l * D3c + 2 * Dc, vmem, Dc, SBc, Dc, Dc, 0);
        gemm(vmem, Dc, ca_out_w + (size_t)l * Dc * Dc, Dc, 0,
             ca_out_b + (size_t)l * Dc, cav, Dc, SBc, Dc, Dc, 0);
        ln_kernel<<<ROWSc, 128>>>(h, cav, ln2_g + (size_t)l * Dc, ln2_b + (size_t)l * Dc, 1);

        // --- FFN ---
        gemm(h, Dc, ff1_w + (size_t)l * Dc * DFFc, DFFc, 0,
             ff1_b + (size_t)l * DFFc, big, DFFc, ROWSc, DFFc, Dc, 1);
        gemm(big, DFFc, ff2_w + (size_t)l * DFFc * Dc, Dc, 0,
             ff2_b + (size_t)l * Dc, bf, Dc, ROWSc, Dc, DFFc, 0);
        ln_kernel<<<ROWSc, 128>>>(h, bf, ln3_g + (size_t)l * Dc, ln3_b + (size_t)l * Dc, 0);
    }

    final_kernel<<<SBc, 128>>>(h, ln_g, ln_b, W_out, b_out, out);
}

// round 3
// speedup vs baseline: 1.8800x; 1.8800x over previous
#include <cuda_runtime.h>
#include <math.h>

// ---------------- problem constants ----------------
#define Bc    32
#define Lc    64
#define Sc    64          // number of steps
#define SBc   2048        // Sc*Bc
#define Dc    512
#define Hc    8
#define HDc   64
#define NLc   8
#define KCB   8192
#define Zc    32
#define DFFc  2048
#define D3c   1536
// packed causal rows: sum_s B*(s+1) = 32 * 2080 = 66560 = 520*128
#define ROWSE 66560

// rowbase for (s,b): 16*s*(s+1) + b*(s+1)
__host__ __device__ __forceinline__ size_t row_base(int s, int b) {
    return (size_t)16 * s * (s + 1) + (size_t)b * (s + 1);
}

// ---------------- scratch (device globals, no allocs) ----------------
__device__ float g_h  [(size_t)ROWSE * Dc];    // hidden state (packed)
__device__ float g_big[(size_t)ROWSE * DFFc];  // qkv (x1536) / ffn hidden (x2048)
__device__ float g_a  [(size_t)ROWSE * Dc];    // attention output
__device__ float g_bf [(size_t)ROWSE * Dc];    // proj outputs
__device__ float g_ctx [(size_t)SBc * Dc];     // ctx_h0 (B*L x D)
__device__ float g_memh[(size_t)SBc * Dc];     // mem_h per (s,b)
__device__ float g_vmem[(size_t)SBc * Dc];     // CA value vector
__device__ float g_cav [(size_t)SBc * Dc];     // CA output vector (broadcast)
__device__ int   g_idx [SBc];
__device__ int   g_rowsb[ROWSE];               // packed row -> s*B+b

// ---------------- SGEMM: C[M,N] = A[M,K] @ W[K,N](col slice) + bias ----------------
// 128x128 tile, BK=8, 256 threads, 8x8 per thread. M%128==0, N%128==0, K%8==0.
__global__ __launch_bounds__(256) void sgemm_kernel(
    const float* __restrict__ A, int lda,
    const float* __restrict__ W, int ldw, int wcol0,
    const float* __restrict__ bias,
    float* __restrict__ C, int ldc,
    int K, int relu)
{
    __shared__ float As[8][128];
    __shared__ float Bs[8][128];
    const int tid = threadIdx.x;
    const int tx = tid & 15;
    const int ty = tid >> 4;
    const size_t rowBase = (size_t)blockIdx.y * 128;
    const int    colBase = blockIdx.x * 128;

    const int arow = tid >> 1;
    const int acol = (tid & 1) << 2;
    const int brow = tid >> 5;
    const int bcol = (tid & 31) << 2;

    const float* Ap = A + (rowBase + arow) * (size_t)lda + acol;
    const float* Wp = W + (size_t)brow * ldw + wcol0 + colBase + bcol;

    float acc[8][8];
#pragma unroll
    for (int i = 0; i < 8; i++)
#pragma unroll
        for (int j = 0; j < 8; j++) acc[i][j] = 0.f;

    for (int k0 = 0; k0 < K; k0 += 8) {
        float4 av = *reinterpret_cast<const float4*>(Ap + k0);
        As[acol + 0][arow] = av.x;
        As[acol + 1][arow] = av.y;
        As[acol + 2][arow] = av.z;
        As[acol + 3][arow] = av.w;
        float4 wv = *reinterpret_cast<const float4*>(Wp + (size_t)k0 * ldw);
        *reinterpret_cast<float4*>(&Bs[brow][bcol]) = wv;
        __syncthreads();
#pragma unroll
        for (int k = 0; k < 8; k++) {
            float ra[8], rb[8];
            float4 a0 = *reinterpret_cast<const float4*>(&As[k][ty * 8]);
            float4 a1 = *reinterpret_cast<const float4*>(&As[k][ty * 8 + 4]);
            float4 b0 = *reinterpret_cast<const float4*>(&Bs[k][tx * 8]);
            float4 b1 = *reinterpret_cast<const float4*>(&Bs[k][tx * 8 + 4]);
            ra[0]=a0.x; ra[1]=a0.y; ra[2]=a0.z; ra[3]=a0.w;
            ra[4]=a1.x; ra[5]=a1.y; ra[6]=a1.z; ra[7]=a1.w;
            rb[0]=b0.x; rb[1]=b0.y; rb[2]=b0.z; rb[3]=b0.w;
            rb[4]=b1.x; rb[5]=b1.y; rb[6]=b1.z; rb[7]=b1.w;
#pragma unroll
            for (int i = 0; i < 8; i++)
#pragma unroll
                for (int j = 0; j < 8; j++)
                    acc[i][j] = fmaf(ra[i], rb[j], acc[i][j]);
        }
        __syncthreads();
    }

#pragma unroll
    for (int i = 0; i < 8; i++) {
        size_t row = rowBase + ty * 8 + i;
#pragma unroll
        for (int j = 0; j < 8; j++) {
            int col = colBase + tx * 8 + j;
            float v = acc[i][j] + bias[col];
            if (relu) v = fmaxf(v, 0.f);
            C[row * (size_t)ldc + col] = v;
        }
    }
}

// ---------------- causal self-attention on packed rows ----------------
// one block per (s*B+b, head); n = s+1 queries & keys, no masking needed.
// smem: Qs(64x65) Ks(64x65) Vs(64x64) Ss(64x64) = 66048 bytes (dynamic)
#define ATTN_SMEM 66048
__global__ void attn_kernel(const float* __restrict__ qkv, float* __restrict__ out)
{
    extern __shared__ float sm[];
    float* Qs = sm;
    float* Ks = sm + 4160;
    float* Vs = sm + 8320;
    float* Ss = sm + 12416;
    const int sb = blockIdx.x;
    const int s  = sb >> 5;
    const int b  = sb & 31;
    const int n  = s + 1;
    const int head = blockIdx.y;
    const int tid = threadIdx.x;
    const size_t rowbase = row_base(s, b);
    const float* base = qkv + rowbase * D3c + head * HDc;

    for (int idx = tid; idx < n * HDc; idx += 256) {
        int l = idx >> 6, d = idx & 63;
        const float* p = base + (size_t)l * D3c;
        Qs[l * 65 + d] = p[d];
        Ks[l * 65 + d] = p[Dc + d];
        Vs[l * 64 + d] = p[2 * Dc + d];
    }
    __syncthreads();

    for (int e = tid; e < n * 64; e += 256) {
        int q = e >> 6, k = e & 63;
        float v = -1e9f;
        if (k < n) {
            float acc = 0.f;
#pragma unroll
            for (int d = 0; d < HDc; d++)
                acc = fmaf(Qs[q * 65 + d], Ks[k * 65 + d], acc);
            v = acc * 0.125f;
        }
        Ss[e] = v;
    }
    __syncthreads();

    const int warp = tid >> 5, lane = tid & 31;
    for (int q = warp; q < n; q += 8) {
        float v0 = Ss[q * 64 + lane];
        float v1 = Ss[q * 64 + 32 + lane];
        float m = fmaxf(v0, v1);
#pragma unroll
        for (int o = 16; o; o >>= 1) m = fmaxf(m, __shfl_xor_sync(0xffffffffu, m, o));
        float e0 = expf(v0 - m);
        float e1 = expf(v1 - m);
        float sum = e0 + e1;
#pragma unroll
        for (int o = 16; o; o >>= 1) sum += __shfl_xor_sync(0xffffffffu, sum, o);
        float inv = 1.f / sum;
        Ss[q * 64 + lane]      = e0 * inv;
        Ss[q * 64 + 32 + lane] = e1 * inv;
    }
    __syncthreads();

    for (int e = tid; e < n * HDc; e += 256) {
        int q = e >> 6, d = e & 63;
        float acc = 0.f;
        for (int k = 0; k < n; k++)
            acc = fmaf(Ss[q * 64 + k], Vs[k * 64 + d], acc);
        out[(rowbase + q) * Dc + head * HDc + d] = acc;
    }
}

// ---------------- residual + LayerNorm (in place on h) ----------------
// bcast=1: t row index = rowsb[r] (CA broadcast per (s,b))
__global__ void ln_kernel(float* __restrict__ h, const float* __restrict__ t,
                          const float* __restrict__ g, const float* __restrict__ bb,
                          const int* __restrict__ rowsb, int bcast)
{
    __shared__ float red[8];
    const int r = blockIdx.x;
    const int tid = threadIdx.x;
    float* hr = h + (size_t)r * Dc;
    const float* tr = t + (size_t)(bcast ? rowsb[r] : r) * Dc;
    float x[4];
    float sum = 0.f;
#pragma unroll
    for (int i = 0; i < 4; i++) { x[i] = hr[tid + i * 128] + tr[tid + i * 128]; sum += x[i]; }
#pragma unroll
    for (int o = 16; o; o >>= 1) sum += __shfl_xor_sync(0xffffffffu, sum, o);
    if ((tid & 31) == 0) red[tid >> 5] = sum;
    __syncthreads();
    float mean = (red[0] + red[1] + red[2] + red[3]) * (1.f / 512.f);
    float vs = 0.f;
#pragma unroll
    for (int i = 0; i < 4; i++) { float d = x[i] - mean; vs = fmaf(d, d, vs); }
#pragma unroll
    for (int o = 16; o; o >>= 1) vs += __shfl_xor_sync(0xffffffffu, vs, o);
    if ((tid & 31) == 0) red[4 + (tid >> 5)] = vs;
    __syncthreads();
    float var = (red[4] + red[5] + red[6] + red[7]) * (1.f / 512.f);
    float inv = rsqrtf(var + 1e-5f);
#pragma unroll
    for (int i = 0; i < 4; i++)
        hr[tid + i * 128] = (x[i] - mean) * inv * g[tid + i * 128] + bb[tid + i * 128];
}

// ---------------- ctx_h0 = x_full[:, :L] @ W_in + b_in + PE ----------------
__global__ void build_ctx_kernel(const float* __restrict__ x,
                                 const float* __restrict__ Win, const float* __restrict__ bin,
                                 float* __restrict__ ctx)
{
    __shared__ float xv[32];
    const int r = blockIdx.x;           // b*L + l
    const int b = r >> 6, l = r & 63;
    if (threadIdx.x < 32)
        xv[threadIdx.x] = (l == 0) ? 0.f : x[((size_t)b * Lc + (l - 1)) * Zc + threadIdx.x];
    __syncthreads();
    const float LOG1E4 = 9.210340371976184f;
    for (int d = threadIdx.x; d < Dc; d += 128) {
        float acc = bin[d];
#pragma unroll
        for (int z = 0; z < Zc; z++)
            acc = fmaf(xv[z], Win[z * Dc + d], acc);
        int d2 = d & ~1;
        float freq = expf(-LOG1E4 * (float)d2 * (1.f / 512.f));
        float ang = (float)l * freq;
        acc += (d & 1) ? cosf(ang) : sinf(ang);
        ctx[(size_t)r * Dc + d] = acc;
    }
}

// ---------------- VQ argmin over codebook ----------------
__global__ void vq_kernel(const float* __restrict__ x, const float* __restrict__ cb,
                          int* __restrict__ idx)
{
    __shared__ float mv[32];
    __shared__ float sd[256];
    __shared__ int   si[256];
    const int sb = blockIdx.x;          // s*B + b
    const int s = sb >> 5, b = sb & 31;
    const int tid = threadIdx.x;
    if (tid < 32) mv[tid] = x[((size_t)b * Lc + s) * Zc + tid];  // mem = x[b, s]
    __syncthreads();
    float bd = 3.4e38f; int bi = 0x7fffffff;
    for (int k = tid; k < KCB; k += 256) {
        const float* c = cb + (size_t)k * Zc;
        float d2 = 0.f;
#pragma unroll
        for (int z = 0; z < Zc; z++) { float df = mv[z] - c[z]; d2 = fmaf(df, df, d2); }
        if (d2 < bd || (d2 == bd && k < bi)) { bd = d2; bi = k; }
    }
    sd[tid] = bd; si[tid] = bi;
    __syncthreads();
    for (int off = 128; off; off >>= 1) {
        if (tid < off) {
            if (sd[tid + off] < sd[tid] ||
                (sd[tid + off] == sd[tid] && si[tid + off] < si[tid])) {
                sd[tid] = sd[tid + off]; si[tid] = si[tid + off];
            }
        }
        __syncthreads();
    }
    if (tid == 0) idx[sb] = si[0];
}

// ---------------- mem_h = codebook[idx] @ W_in + b_in ----------------
__global__ void build_memh_kernel(const float* __restrict__ cb, const int* __restrict__ idx,
                                  const float* __restrict__ Win, const float* __restrict__ bin,
                                  float* __restrict__ memh)
{
    __shared__ float qv[32];
    const int sb = blockIdx.x;
    if (threadIdx.x < 32)
        qv[threadIdx.x] = cb[(size_t)idx[sb] * Zc + threadIdx.x];
    __syncthreads();
    for (int d = threadIdx.x; d < Dc; d += 128) {
        float acc = bin[d];
#pragma unroll
        for (int z = 0; z < Zc; z++)
            acc = fmaf(qv[z], Win[z * Dc + d], acc);
        memh[(size_t)sb * Dc + d] = acc;
    }
}

// ---------------- init packed h from ctx + row->sb map ----------------
__global__ void build_h_kernel(const float* __restrict__ ctx, float* __restrict__ h,
                               int* __restrict__ rowsb)
{
    const int sb = blockIdx.x;
    const int s = sb >> 5, b = sb & 31;
    const int n = s + 1;
    const size_t base = row_base(s, b);
    // ctx rows for batch b are contiguous in l -> straight copy of n*Dc floats
    const float* src = ctx + ((size_t)b * Lc) * Dc;
    float* dst = h + base * Dc;
    const int tot = n * Dc;
    for (int i = threadIdx.x; i < tot; i += 256)
        dst[i] = src[i];
    for (int l = threadIdx.x; l < n; l += 256)
        rowsb[base + l] = sb;
}

// ---------------- final: LN(h[row(s,b,l=s)]) @ W_out + b_out -> out[b,s,:] ----------------
__global__ void final_kernel(const float* __restrict__ h,
                             const float* __restrict__ g, const float* __restrict__ bb,
                             const float* __restrict__ Wout, const float* __restrict__ bout,
                             float* __restrict__ out)
{
    __shared__ float red[8];
    __shared__ float tv[512];
    __shared__ float part[128];
    const int sb = blockIdx.x;
    const int s = sb >> 5, b = sb & 31;
    const int tid = threadIdx.x;
    const float* hr = h + (row_base(s, b) + s) * Dc;
    float x[4]; float sum = 0.f;
#pragma unroll
    for (int i = 0; i < 4; i++) { x[i] = hr[tid + i * 128]; sum += x[i]; }
#pragma unroll
    for (int o = 16; o; o >>= 1) sum += __shfl_xor_sync(0xffffffffu, sum, o);
    if ((tid & 31) == 0) red[tid >> 5] = sum;
    __syncthreads();
    float mean = (red[0] + red[1] + red[2] + red[3]) * (1.f / 512.f);
    float vs = 0.f;
#pragma unroll
    for (int i = 0; i < 4; i++) { float d = x[i] - mean; vs = fmaf(d, d, vs); }
#pragma unroll
    for (int o = 16; o; o >>= 1) vs += __shfl_xor_sync(0xffffffffu, vs, o);
    if ((tid & 31) == 0) red[4 + (tid >> 5)] = vs;
    __syncthreads();
    float var = (red[4] + red[5] + red[6] + red[7]) * (1.f / 512.f);
    float inv = rsqrtf(var + 1e-5f);
#pragma unroll
    for (int i = 0; i < 4; i++)
        tv[tid + i * 128] = (x[i] - mean) * inv * g[tid + i * 128] + bb[tid + i * 128];
    __syncthreads();
    const int z = tid & 31, c = tid >> 5;
    float acc = 0.f;
    for (int k = c * 128; k < c * 128 + 128; k++)
        acc = fmaf(tv[k], Wout[(size_t)k * Zc + z], acc);
    part[tid] = acc;
    __syncthreads();
    if (tid < 32)
        out[((size_t)b * Lc + s) * Zc + z] =
            part[z] + part[32 + z] + part[64 + z] + part[96 + z] + bout[z];
}

// ---------------- host ----------------
static inline void gemm(const float* A, int lda, const float* W, int ldw, int wcol0,
                        const float* bias, float* C, int ldc, int M, int N, int K, int relu)
{
    dim3 grid(N / 128, M / 128);
    sgemm_kernel<<<grid, 256>>>(A, lda, W, ldw, wcol0, bias, C, ldc, K, relu);
}

extern "C" void kernel_launch(void* const* d_in, const int* in_sizes, int n_in,
                              void* d_out, int out_size)
{
    const float* x        = (const float*)d_in[0];
    const float* codebook = (const float*)d_in[1];
    const float* W_in     = (const float*)d_in[2];
    const float* b_in     = (const float*)d_in[3];
    const float* sa_qkv_w = (const float*)d_in[4];
    const float* sa_qkv_b = (const float*)d_in[5];
    const float* sa_out_w = (const float*)d_in[6];
    const float* sa_out_b = (const float*)d_in[7];
    const float* ca_qkv_w = (const float*)d_in[8];
    const float* ca_qkv_b = (const float*)d_in[9];
    const float* ca_out_w = (const float*)d_in[10];
    const float* ca_out_b = (const float*)d_in[11];
    const float* ff1_w    = (const float*)d_in[12];
    const float* ff1_b    = (const float*)d_in[13];
    const float* ff2_w    = (const float*)d_in[14];
    const float* ff2_b    = (const float*)d_in[15];
    const float* ln1_g    = (const float*)d_in[16];
    const float* ln1_b    = (const float*)d_in[17];
    const float* ln2_g    = (const float*)d_in[18];
    const float* ln2_b    = (const float*)d_in[19];
    const float* ln3_g    = (const float*)d_in[20];
    const float* ln3_b    = (const float*)d_in[21];
    const float* ln_g     = (const float*)d_in[22];
    const float* ln_b     = (const float*)d_in[23];
    const float* W_out    = (const float*)d_in[24];
    const float* b_out    = (const float*)d_in[25];
    float* out = (float*)d_out;

    float *h, *big, *a, *bf, *ctx, *memh, *vmem, *cav; int *idx, *rowsb;
    cudaGetSymbolAddress((void**)&h,    g_h);
    cudaGetSymbolAddress((void**)&big,  g_big);
    cudaGetSymbolAddress((void**)&a,    g_a);
    cudaGetSymbolAddress((void**)&bf,   g_bf);
    cudaGetSymbolAddress((void**)&ctx,  g_ctx);
    cudaGetSymbolAddress((void**)&memh, g_memh);
    cudaGetSymbolAddress((void**)&vmem, g_vmem);
    cudaGetSymbolAddress((void**)&cav,  g_cav);
    cudaGetSymbolAddress((void**)&idx,  g_idx);
    cudaGetSymbolAddress((void**)&rowsb, g_rowsb);

    cudaFuncSetAttribute(attn_kernel, cudaFuncAttributeMaxDynamicSharedMemorySize, ATTN_SMEM);

    build_ctx_kernel<<<SBc, 128>>>(x, W_in, b_in, ctx);
    vq_kernel<<<SBc, 256>>>(x, codebook, idx);
    build_memh_kernel<<<SBc, 128>>>(codebook, idx, W_in, b_in, memh);
    build_h_kernel<<<SBc, 256>>>(ctx, h, rowsb);

    for (int l = 0; l < NLc; l++) {
        // --- self-attention ---
        gemm(h, Dc, sa_qkv_w + (size_t)l * Dc * D3c, D3c, 0,
             sa_qkv_b + (size_t)l * D3c, big, D3c, ROWSE, D3c, Dc, 0);
        attn_kernel<<<dim3(SBc, Hc), 256, ATTN_SMEM>>>(big, a);
        gemm(a, Dc, sa_out_w + (size_t)l * Dc * Dc, Dc, 0,
             sa_out_b + (size_t)l * Dc, bf, Dc, ROWSE, Dc, Dc, 0);
        ln_kernel<<<ROWSE, 128>>>(h, bf, ln1_g + (size_t)l * Dc, ln1_b + (size_t)l * Dc, rowsb, 0);

        // --- cross-attention (softmax over 1 key == identity -> pure value path) ---
        gemm(memh, Dc, ca_qkv_w + (size_t)l * Dc * D3c, D3c, 2 * Dc,
             ca_qkv_b + (size_t)l * D3c + 2 * Dc, vmem, Dc, SBc, Dc, Dc, 0);
        gemm(vmem, Dc, ca_out_w + (size_t)l * Dc * Dc, Dc, 0,
             ca_out_b + (size_t)l * Dc, cav, Dc, SBc, Dc, Dc, 0);
        ln_kernel<<<ROWSE, 128>>>(h, cav, ln2_g + (size_t)l * Dc, ln2_b + (size_t)l * Dc, rowsb, 1);

        // --- FFN ---
        gemm(h, Dc, ff1_w + (size_t)l * Dc * DFFc, DFFc, 0,
             ff1_b + (size_t)l * DFFc, big, DFFc, ROWSE, DFFc, Dc, 1);
        gemm(big, DFFc, ff2_w + (size_t)l * DFFc * Dc, Dc, 0,
             ff2_b + (size_t)l * Dc, bf, Dc, ROWSE, Dc, DFFc, 0);
        ln_kernel<<<ROWSE, 128>>>(h, bf, ln3_g + (size_t)l * Dc, ln3_b + (size_t)l * Dc, rowsb, 0);
    }

    final_kernel<<<SBc, 128>>>(h, ln_g, ln_b, W_out, b_out, out);
}